// round 3
// baseline (speedup 1.0000x reference)
#include <cuda_runtime.h>

// Problem constants (fixed by the dataset problem)
#define D_DIM   512
#define V_DIM   1024
#define KSTAGES 4

#define BM 128
#define BV 128
#define BK 8

// ||c||^2 for every codebook vector (near-correctly-rounded fp32)
__device__ float g_c2[KSTAGES * V_DIM];

// ---------------------------------------------------------------------------
// c2 kernel: one warp per codebook vector, double accumulation of fl(c*c)
// ---------------------------------------------------------------------------
__global__ void rvq_c2_kernel(const float* __restrict__ cb) {
    int w = (blockIdx.x * blockDim.x + threadIdx.x) >> 5;
    int lane = threadIdx.x & 31;
    if (w >= KSTAGES * V_DIM) return;
    const float* v = cb + (size_t)w * D_DIM;
    double s = 0.0;
    for (int i = lane; i < D_DIM; i += 32) {
        float t = v[i];
        float p = __fmul_rn(t, t);   // reference sums rounded elementwise squares
        s += (double)p;
    }
    #pragma unroll
    for (int o = 16; o > 0; o >>= 1)
        s += __shfl_xor_sync(0xffffffffu, s, o);
    if (lane == 0) g_c2[w] = (float)s;
}

// packed f32x2 FMA: d = a*b + d (elementwise on 2 packed floats)
#define FFMA2(acc_, a_, b_) \
    asm("fma.rn.f32x2 %0, %1, %2, %3;" : "=l"(acc_) : "l"(a_), "l"(b_), "l"(acc_))

__device__ __forceinline__ unsigned long long dup_f32(float a) {
    unsigned long long r;
    unsigned int ai = __float_as_uint(a);
    asm("mov.b64 %0, {%1, %2};" : "=l"(r) : "r"(ai), "r"(ai));
    return r;
}

__device__ __forceinline__ void unpack2(unsigned long long p, float& lo, float& hi) {
    unsigned int l, h;
    asm("mov.b64 {%0, %1}, %2;" : "=r"(l), "=r"(h) : "l"(p));
    lo = __uint_as_float(l);
    hi = __uint_as_float(h);
}

// Kahan compensated add (all roundings explicit, no contraction)
__device__ __forceinline__ void kahan_add(float& s, float& c, float y) {
    float t1 = __fsub_rn(y, c);
    float t2 = __fadd_rn(s, t1);
    c = __fsub_rn(__fsub_rn(t2, s), t1);
    s = t2;
}

// ---------------------------------------------------------------------------
// Fused stage kernel: for 128 rows, compute
//   d[v] = RN( RN(r2 - 2*dot) + c2[v] )   (matches jax evaluation order)
// argmin over V=1024 (first-index tie-break), write code, update residual.
// ---------------------------------------------------------------------------
__global__ __launch_bounds__(256, 2) void rvq_stage_kernel(
    const float* __restrict__ resin,   // [N, 512]
    float*       __restrict__ resout,  // [N, 512] (may alias resin)
    const float* __restrict__ cb,      // [1024, 512] this stage's codebook
    float*       __restrict__ codes,   // [N, 4] as float
    int stage)
{
    __shared__ float As[BK][BM];
    __shared__ float Bs[BK][BV];
    __shared__ float sC2[BV];
    __shared__ float sR2[BM];
    __shared__ float redV[BM][17];
    __shared__ int   redI[BM][17];
    __shared__ float bestV[BM];
    __shared__ int   bestI[BM];

    const int tid = threadIdx.x;
    const int row0 = blockIdx.x * BM;
    const int tx = tid & 15;   // v sub-tile
    const int ty = tid >> 4;   // m sub-tile

    if (tid < BM) { bestV[tid] = 3.4e38f; bestI[tid] = 0; }

    // --- r2 per row (Kahan fp32 ~ correctly rounded sum of fl(x*x)) ---
    if (tid < BM) {
        const float4* rp = (const float4*)&resin[(size_t)(row0 + tid) * D_DIM];
        float s = 0.f, c = 0.f;
        #pragma unroll 4
        for (int i = 0; i < D_DIM / 4; i++) {
            float4 v = rp[i];
            kahan_add(s, c, __fmul_rn(v.x, v.x));
            kahan_add(s, c, __fmul_rn(v.y, v.y));
            kahan_add(s, c, __fmul_rn(v.z, v.z));
            kahan_add(s, c, __fmul_rn(v.w, v.w));
        }
        sR2[tid] = __fadd_rn(s, c);
    }
    __syncthreads();

    const int lr = tid >> 1;        // 0..127: tile row for global loads
    const int lk = (tid & 1) * 4;   // 0 or 4

    // r2 for this thread's 8 rows (4 pairs of adjacent rows)
    float r2p[4][2];
    #pragma unroll
    for (int ip = 0; ip < 4; ip++) {
        int r = (ip < 2) ? (ty * 4 + 2 * ip) : (64 + ty * 4 + 2 * (ip - 2));
        r2p[ip][0] = sR2[r];
        r2p[ip][1] = sR2[r + 1];
    }

    for (int vb = 0; vb < V_DIM; vb += BV) {
        if (tid < BV) sC2[tid] = g_c2[stage * V_DIM + vb + tid];

        // acc[ip][j]: packed pair of rows, 4 row-pairs x 8 cols
        unsigned long long acc[4][8];
        #pragma unroll
        for (int ip = 0; ip < 4; ip++)
            #pragma unroll
            for (int j = 0; j < 8; j++) acc[ip][j] = 0ull;

        for (int kb = 0; kb < D_DIM; kb += BK) {
            __syncthreads();
            {
                float4 av = *(const float4*)&resin[(size_t)(row0 + lr) * D_DIM + kb + lk];
                As[lk + 0][lr] = av.x;
                As[lk + 1][lr] = av.y;
                As[lk + 2][lr] = av.z;
                As[lk + 3][lr] = av.w;
            }
            {
                float4 bv = *(const float4*)&cb[(size_t)(vb + lr) * D_DIM + kb + lk];
                Bs[lk + 0][lr] = bv.x;
                Bs[lk + 1][lr] = bv.y;
                Bs[lk + 2][lr] = bv.z;
                Bs[lk + 3][lr] = bv.w;
            }
            __syncthreads();

            #pragma unroll
            for (int k = 0; k < BK; k++) {
                ulonglong2 A0 = *(const ulonglong2*)&As[k][ty * 4];
                ulonglong2 A1 = *(const ulonglong2*)&As[k][64 + ty * 4];
                unsigned long long ap[4] = {A0.x, A0.y, A1.x, A1.y};
                float4 b0 = *(const float4*)&Bs[k][tx * 4];
                float4 b1 = *(const float4*)&Bs[k][64 + tx * 4];
                unsigned long long bd[8];
                bd[0] = dup_f32(b0.x); bd[1] = dup_f32(b0.y);
                bd[2] = dup_f32(b0.z); bd[3] = dup_f32(b0.w);
                bd[4] = dup_f32(b1.x); bd[5] = dup_f32(b1.y);
                bd[6] = dup_f32(b1.z); bd[7] = dup_f32(b1.w);
                #pragma unroll
                for (int ip = 0; ip < 4; ip++)
                    #pragma unroll
                    for (int j = 0; j < 8; j++)
                        FFMA2(acc[ip][j], ap[ip], bd[j]);
            }
        }

        // local argmin per row over this v-chunk, ascending v order, strict <
        // score = RN( RN(r2 - 2*dot) + c2 )  -- matches reference rounding
        #pragma unroll
        for (int ip = 0; ip < 4; ip++) {
            float bvlo = 3.4e38f, bvhi = 3.4e38f;
            int bilo = 0, bihi = 0;
            #pragma unroll
            for (int j = 0; j < 8; j++) {
                int vc = (j < 4) ? (tx * 4 + j) : (64 + tx * 4 + (j - 4));
                float lo, hi;
                unpack2(acc[ip][j], lo, hi);
                float c2v = sC2[vc];
                // 2*dot is exact (exponent bump); sub rounds once; add rounds once
                float slo = __fadd_rn(__fsub_rn(r2p[ip][0], __fmul_rn(2.f, lo)), c2v);
                float shi = __fadd_rn(__fsub_rn(r2p[ip][1], __fmul_rn(2.f, hi)), c2v);
                if (slo < bvlo) { bvlo = slo; bilo = vc; }
                if (shi < bvhi) { bvhi = shi; bihi = vc; }
            }
            int rlo = (ip < 2) ? (ty * 4 + 2 * ip) : (64 + ty * 4 + 2 * (ip - 2));
            redV[rlo][tx] = bvlo;       redI[rlo][tx] = vb + bilo;
            redV[rlo + 1][tx] = bvhi;   redI[rlo + 1][tx] = vb + bihi;
        }
        __syncthreads();

        // cross-thread reduce (16 partials per row), first-index tie-break
        if (tid < BM) {
            float bv = bestV[tid];
            int bi = bestI[tid];
            #pragma unroll
            for (int t = 0; t < 16; t++) {
                float v = redV[tid][t];
                int i = redI[tid][t];
                if (v < bv || (v == bv && i < bi)) { bv = v; bi = i; }
            }
            bestV[tid] = bv;
            bestI[tid] = bi;
        }
        __syncthreads();
    }

    // write codes (as float, int32 values are exact in fp32)
    if (tid < BM) codes[(size_t)(row0 + tid) * KSTAGES + stage] = (float)bestI[tid];
    __syncthreads();

    // residual update: resout[row] = resin[row] - cb[best[row]]  (exact same
    // elementwise fp32 subtraction as the reference)
    const int urow_off = tid >> 7;           // 0 or 1
    const int ucol = (tid & 127) * 4;        // covers all 512 cols
    for (int r = 0; r < BM; r += 2) {
        int row = r + urow_off;
        int best = bestI[row];
        const float4 rv = *(const float4*)&resin[(size_t)(row0 + row) * D_DIM + ucol];
        const float4 qv = *(const float4*)&cb[(size_t)best * D_DIM + ucol];
        float4 o;
        o.x = __fsub_rn(rv.x, qv.x); o.y = __fsub_rn(rv.y, qv.y);
        o.z = __fsub_rn(rv.z, qv.z); o.w = __fsub_rn(rv.w, qv.w);
        *(float4*)&resout[(size_t)(row0 + row) * D_DIM + ucol] = o;
    }
}

// ---------------------------------------------------------------------------
// quantized = x - residual
// ---------------------------------------------------------------------------
__global__ void rvq_quant_kernel(const float4* __restrict__ x,
                                 const float4* __restrict__ res,
                                 float4* __restrict__ q, int n4) {
    int i = blockIdx.x * blockDim.x + threadIdx.x;
    if (i < n4) {
        float4 a = x[i], b = res[i];
        float4 o;
        o.x = __fsub_rn(a.x, b.x); o.y = __fsub_rn(a.y, b.y);
        o.z = __fsub_rn(a.z, b.z); o.w = __fsub_rn(a.w, b.w);
        q[i] = o;
    }
}

extern "C" void kernel_launch(void* const* d_in, const int* in_sizes, int n_in,
                              void* d_out, int out_size) {
    const float* x   = (const float*)d_in[0];       // [N, 512]
    const float* cbs = (const float*)d_in[1];       // [4, 1024, 512]
    const int N = in_sizes[0] / D_DIM;

    float* out   = (float*)d_out;
    float* codes = out;                                   // [N, 4]
    float* quant = out + (size_t)N * KSTAGES;             // [N, 512]
    float* res   = quant + (size_t)N * D_DIM;             // [N, 512]

    // 1) codebook squared norms
    rvq_c2_kernel<<<(KSTAGES * V_DIM * 32 + 255) / 256, 256>>>(cbs);

    // 2) four sequential fused GEMM+argmin+update stages (residual in place)
    for (int s = 0; s < KSTAGES; s++) {
        const float* rin = (s == 0) ? x : res;
        rvq_stage_kernel<<<N / BM, 256>>>(
            rin, res, cbs + (size_t)s * V_DIM * D_DIM, codes, s);
    }

    // 3) quantized = x - residual
    int n4 = N * D_DIM / 4;
    rvq_quant_kernel<<<(n4 + 255) / 256, 256>>>(
        (const float4*)x, (const float4*)res, (float4*)quant, n4);
}